// round 3
// baseline (speedup 1.0000x reference)
#include <cuda_runtime.h>
#include <cuda_bf16.h>
#include <cstdint>

// Problem constants
#define C1_IN 8
#define C_OUT 64
#define NN 16384

// Intermediate h = output of layer 1: [N, 64]. Static device scratch.
__device__ float g_h[NN * 64];

__device__ __forceinline__ int clamp_idx(int v, int n) {
    v = v < 0 ? 0 : v;
    return v >= n ? n - 1 : v;
}

// ---------------------------------------------------------------------------
// K1: h[n,o] = sum_i x[n,i] * root1[i,o] + bias1[o]
// ---------------------------------------------------------------------------
__global__ void k_node1(const float* __restrict__ x,
                        const float* __restrict__ root1,
                        const float* __restrict__ bias1,
                        int N)
{
    int idx = blockIdx.x * blockDim.x + threadIdx.x;
    if (idx >= N * 64) return;
    int n = idx >> 6;
    int o = idx & 63;
    const float* xr = x + n * C1_IN;
    float acc = __ldg(&bias1[o]);
#pragma unroll
    for (int i = 0; i < C1_IN; i++)
        acc = fmaf(__ldg(&xr[i]), __ldg(&root1[i * 64 + o]), acc);
    g_h[idx] = acc;
}

// ---------------------------------------------------------------------------
// K2: layer-1 edge kernel. One warp per edge.
//   msg[o] = sum_{i<8} x[src,i] * relu(a0*A1[0,i*64+o] + a1*A1[1,i*64+o] + b1[i*64+o])
//   red-add into g_h[dst*64+o]. Lane handles o = 2*lane, 2*lane+1.
// ---------------------------------------------------------------------------
__global__ void k_edge1(const float* __restrict__ x,
                        const int* __restrict__ ei,
                        const float* __restrict__ ea,
                        const float* __restrict__ A1,
                        const float* __restrict__ b1,
                        int E, int N)
{
    __shared__ float sA[512 * 3];  // A1 row0 | A1 row1 | b1
    for (int i = threadIdx.x; i < 512; i += blockDim.x) {
        sA[i]        = A1[i];
        sA[512 + i]  = A1[512 + i];
        sA[1024 + i] = b1[i];
    }
    __syncthreads();

    const int warp = threadIdx.x >> 5;
    const int lane = threadIdx.x & 31;
    const int wpb  = blockDim.x >> 5;

    const float2* w0p = reinterpret_cast<const float2*>(sA);
    const float2* w1p = reinterpret_cast<const float2*>(sA + 512);
    const float2* bbp = reinterpret_cast<const float2*>(sA + 1024);

    for (int e = blockIdx.x * wpb + warp; e < E; e += gridDim.x * wpb) {
        int src = clamp_idx(ei[e], N);
        int dst = clamp_idx(ei[E + e], N);
        float2 a = *reinterpret_cast<const float2*>(ea + 2 * e);
        float xv = (lane < C1_IN) ? x[src * C1_IN + lane] : 0.0f;

        float acc0 = 0.0f, acc1 = 0.0f;
#pragma unroll
        for (int i = 0; i < C1_IN; i++) {
            float xi = __shfl_sync(0xffffffffu, xv, i);
            float2 w0 = w0p[i * 32 + lane];
            float2 w1 = w1p[i * 32 + lane];
            float2 bb = bbp[i * 32 + lane];
            float u0 = fmaxf(fmaf(a.y, w1.x, fmaf(a.x, w0.x, bb.x)), 0.0f);
            float u1 = fmaxf(fmaf(a.y, w1.y, fmaf(a.x, w0.y, bb.y)), 0.0f);
            acc0 = fmaf(xi, u0, acc0);
            acc1 = fmaf(xi, u1, acc1);
        }
        float* p = g_h + (size_t)dst * 64 + 2 * lane;
        asm volatile("red.global.add.v2.f32 [%0], {%1, %2};"
                     :: "l"(p), "f"(acc0), "f"(acc1) : "memory");
    }
}

// ---------------------------------------------------------------------------
// K3: out[n,o] = sum_i h[n,i] * root2[i,o] + bias2[o]
// ---------------------------------------------------------------------------
__global__ void k_node2(const float* __restrict__ root2,
                        const float* __restrict__ bias2,
                        float* __restrict__ out,
                        int N)
{
    __shared__ float r2[4096];
    for (int i = threadIdx.x; i < 4096; i += blockDim.x)
        r2[i] = root2[i];
    __syncthreads();

    const int o = threadIdx.x & 63;
    const int j = threadIdx.x >> 6;  // 0..3
    const float bv = __ldg(&bias2[o]);

    for (int nb = blockIdx.x * 4; nb < N; nb += gridDim.x * 4) {
        int n = nb + j;
        if (n >= N) continue;
        const float4* hr = reinterpret_cast<const float4*>(g_h + (size_t)n * 64);
        float acc = bv;
#pragma unroll
        for (int q = 0; q < 16; q++) {
            float4 hv = hr[q];
            acc = fmaf(hv.x, r2[(q * 4 + 0) * 64 + o], acc);
            acc = fmaf(hv.y, r2[(q * 4 + 1) * 64 + o], acc);
            acc = fmaf(hv.z, r2[(q * 4 + 2) * 64 + o], acc);
            acc = fmaf(hv.w, r2[(q * 4 + 3) * 64 + o], acc);
        }
        out[(size_t)n * 64 + o] = acc;
    }
}

// ---------------------------------------------------------------------------
// K4: layer-2 edge kernel (the heavy one).
//   msg[o] = sum_{i<64} h[src,i] * relu(a0*A2[0,i*64+o] + a1*A2[1,i*64+o] + b2[i*64+o])
// 128 threads: thread = (o = tid&63, g = tid>>6). A2/b2 slice in 96 regs.
// ---------------------------------------------------------------------------
#define L2_EPB 4

__global__ __launch_bounds__(128, 3)
void k_edge2(const int* __restrict__ ei,
             const float* __restrict__ ea,
             const float* __restrict__ A2,
             const float* __restrict__ b2,
             float* __restrict__ out,
             int E, int N)
{
    const int tid = threadIdx.x;
    const int o = tid & 63;
    const int g = tid >> 6;  // 0 or 1

    float A0r[32], A1r[32], Br[32];
#pragma unroll
    for (int k = 0; k < 32; k++) {
        int col = (g * 32 + k) * 64 + o;
        A0r[k] = __ldg(&A2[col]);
        A1r[k] = __ldg(&A2[4096 + col]);
        Br[k]  = __ldg(&b2[col]);
    }

    __shared__ float hs[L2_EPB][64];
    __shared__ float pr[L2_EPB][64];
    __shared__ float msg[L2_EPB][64];
    __shared__ int   sSrc[L2_EPB];
    __shared__ int   sDst[L2_EPB];
    __shared__ float sA0[L2_EPB];
    __shared__ float sA1[L2_EPB];

    for (int e0 = blockIdx.x * L2_EPB; e0 < E; e0 += gridDim.x * L2_EPB) {
        if (tid < L2_EPB) {
            int e = e0 + tid;
            if (e < E) {
                sSrc[tid] = clamp_idx(ei[e], N);
                sDst[tid] = clamp_idx(ei[E + e], N);
                float2 a = *reinterpret_cast<const float2*>(ea + 2 * e);
                sA0[tid] = a.x;
                sA1[tid] = a.y;
            } else {
                sSrc[tid] = 0;
                sDst[tid] = 0;
                sA0[tid] = 0.0f;
                sA1[tid] = 0.0f;
            }
        }
        __syncthreads();

        // Gather h[src] rows: 4 edges x 64 floats, 128 threads x 2.
        {
            int idx = tid;
#pragma unroll
            for (int r = 0; r < 2; r++) {
                int j = idx >> 6, c = idx & 63;
                hs[j][c] = g_h[(size_t)sSrc[j] * 64 + c];
                idx += 128;
            }
        }
        __syncthreads();

        float a0[L2_EPB], a1[L2_EPB], acc[L2_EPB];
#pragma unroll
        for (int j = 0; j < L2_EPB; j++) {
            a0[j] = sA0[j];
            a1[j] = sA1[j];
            acc[j] = 0.0f;
        }

#pragma unroll
        for (int k = 0; k < 32; k++) {
#pragma unroll
            for (int j = 0; j < L2_EPB; j++) {
                float w = fmaf(a1[j], A1r[k], fmaf(a0[j], A0r[k], Br[k]));
                w = fmaxf(w, 0.0f);
                acc[j] = fmaf(hs[j][g * 32 + k], w, acc[j]);
            }
        }

        if (g == 1) {
#pragma unroll
            for (int j = 0; j < L2_EPB; j++) pr[j][o] = acc[j];
        }
        __syncthreads();
        if (g == 0) {
#pragma unroll
            for (int j = 0; j < L2_EPB; j++) msg[j][o] = acc[j] + pr[j][o];
        }
        __syncthreads();

        if (tid < 64) {
            int j = tid >> 4, q = tid & 15;
            if (e0 + j < E) {
                float4 v = *reinterpret_cast<const float4*>(&msg[j][q * 4]);
                float* dstp = out + (size_t)sDst[j] * 64 + q * 4;
                asm volatile("red.global.add.v4.f32 [%0], {%1, %2, %3, %4};"
                             :: "l"(dstp), "f"(v.x), "f"(v.y), "f"(v.z), "f"(v.w)
                             : "memory");
            }
        }
        __syncthreads();
    }
}

// ---------------------------------------------------------------------------
// Launch
// ---------------------------------------------------------------------------
extern "C" void kernel_launch(void* const* d_in, const int* in_sizes, int n_in,
                              void* d_out, int out_size)
{
    const float* x     = (const float*)d_in[0];
    const int*   ei    = (const int*)d_in[1];     // int32 (JAX x64 disabled)
    const float* ea    = (const float*)d_in[2];
    const float* A1    = (const float*)d_in[3];
    const float* b1    = (const float*)d_in[4];
    const float* A2    = (const float*)d_in[5];
    const float* b2    = (const float*)d_in[6];
    const float* root1 = (const float*)d_in[7];
    const float* bias1 = (const float*)d_in[8];
    const float* root2 = (const float*)d_in[9];
    const float* bias2 = (const float*)d_in[10];
    float* out = (float*)d_out;

    const int N = in_sizes[0] / C1_IN;   // 16384
    const int E = in_sizes[1] / 2;       // 65536

    {
        int total = N * 64;
        int blocks = (total + 255) / 256;
        k_node1<<<blocks, 256>>>(x, root1, bias1, N);
    }
    k_edge1<<<1024, 256>>>(x, ei, ea, A1, b1, E, N);
    k_node2<<<512, 256>>>(root2, bias2, out, N);
    k_edge2<<<444, 128>>>(ei, ea, A2, b2, out, E, N);
}

// round 5
// speedup vs baseline: 1.0027x; 1.0027x over previous
#include <cuda_runtime.h>
#include <cuda_bf16.h>
#include <cstdint>

// Problem constants
#define C1_IN 8
#define C_OUT 64
#define NN 16384

// Intermediate h = output of layer 1: [N, 64]. Static device scratch.
__device__ float g_h[NN * 64];

__device__ __forceinline__ int clamp_idx(int v, int n) {
    v = v < 0 ? 0 : v;
    return v >= n ? n - 1 : v;
}

// ---------------------------------------------------------------------------
// K1: h[n,o] = sum_i x[n,i] * root1[i,o] + bias1[o]
// ---------------------------------------------------------------------------
__global__ void k_node1(const float* __restrict__ x,
                        const float* __restrict__ root1,
                        const float* __restrict__ bias1,
                        int N)
{
    int idx = blockIdx.x * blockDim.x + threadIdx.x;
    if (idx >= N * 64) return;
    int n = idx >> 6;
    int o = idx & 63;
    const float* xr = x + n * C1_IN;
    float acc = __ldg(&bias1[o]);
#pragma unroll
    for (int i = 0; i < C1_IN; i++)
        acc = fmaf(__ldg(&xr[i]), __ldg(&root1[i * 64 + o]), acc);
    g_h[idx] = acc;
}

// ---------------------------------------------------------------------------
// K2: layer-1 edge kernel. One warp per edge.
//   msg[o] = sum_{i<8} x[src,i] * relu(a0*A1[0,i*64+o] + a1*A1[1,i*64+o] + b1[i*64+o])
//   red-add into g_h[dst*64+o]. Lane handles o = 2*lane, 2*lane+1.
// ---------------------------------------------------------------------------
__global__ void k_edge1(const float* __restrict__ x,
                        const int* __restrict__ ei,
                        const float* __restrict__ ea,
                        const float* __restrict__ A1,
                        const float* __restrict__ b1,
                        int E, int N)
{
    __shared__ float sA[512 * 3];  // A1 row0 | A1 row1 | b1
    for (int i = threadIdx.x; i < 512; i += blockDim.x) {
        sA[i]        = A1[i];
        sA[512 + i]  = A1[512 + i];
        sA[1024 + i] = b1[i];
    }
    __syncthreads();

    const int warp = threadIdx.x >> 5;
    const int lane = threadIdx.x & 31;
    const int wpb  = blockDim.x >> 5;

    const float2* w0p = reinterpret_cast<const float2*>(sA);
    const float2* w1p = reinterpret_cast<const float2*>(sA + 512);
    const float2* bbp = reinterpret_cast<const float2*>(sA + 1024);

    for (int e = blockIdx.x * wpb + warp; e < E; e += gridDim.x * wpb) {
        int src = clamp_idx(ei[e], N);
        int dst = clamp_idx(ei[E + e], N);
        float2 a = *reinterpret_cast<const float2*>(ea + 2 * e);
        float xv = (lane < C1_IN) ? x[src * C1_IN + lane] : 0.0f;

        float acc0 = 0.0f, acc1 = 0.0f;
#pragma unroll
        for (int i = 0; i < C1_IN; i++) {
            float xi = __shfl_sync(0xffffffffu, xv, i);
            float2 w0 = w0p[i * 32 + lane];
            float2 w1 = w1p[i * 32 + lane];
            float2 bb = bbp[i * 32 + lane];
            float u0 = fmaxf(fmaf(a.y, w1.x, fmaf(a.x, w0.x, bb.x)), 0.0f);
            float u1 = fmaxf(fmaf(a.y, w1.y, fmaf(a.x, w0.y, bb.y)), 0.0f);
            acc0 = fmaf(xi, u0, acc0);
            acc1 = fmaf(xi, u1, acc1);
        }
        float* p = g_h + (size_t)dst * 64 + 2 * lane;
        asm volatile("red.global.add.v2.f32 [%0], {%1, %2};"
                     :: "l"(p), "f"(acc0), "f"(acc1) : "memory");
    }
}

// ---------------------------------------------------------------------------
// K3: out[n,o] = sum_i h[n,i] * root2[i,o] + bias2[o]
// ---------------------------------------------------------------------------
__global__ void k_node2(const float* __restrict__ root2,
                        const float* __restrict__ bias2,
                        float* __restrict__ out,
                        int N)
{
    __shared__ float r2[4096];
    for (int i = threadIdx.x; i < 4096; i += blockDim.x)
        r2[i] = root2[i];
    __syncthreads();

    const int o = threadIdx.x & 63;
    const int j = threadIdx.x >> 6;  // 0..3
    const float bv = __ldg(&bias2[o]);

    for (int nb = blockIdx.x * 4; nb < N; nb += gridDim.x * 4) {
        int n = nb + j;
        if (n >= N) continue;
        const float4* hr = reinterpret_cast<const float4*>(g_h + (size_t)n * 64);
        float acc = bv;
#pragma unroll
        for (int q = 0; q < 16; q++) {
            float4 hv = hr[q];
            acc = fmaf(hv.x, r2[(q * 4 + 0) * 64 + o], acc);
            acc = fmaf(hv.y, r2[(q * 4 + 1) * 64 + o], acc);
            acc = fmaf(hv.z, r2[(q * 4 + 2) * 64 + o], acc);
            acc = fmaf(hv.w, r2[(q * 4 + 3) * 64 + o], acc);
        }
        out[(size_t)n * 64 + o] = acc;
    }
}

// ---------------------------------------------------------------------------
// K4: layer-2 edge kernel (the heavy one).
//   msg[o] = sum_{i<64} h[src,i] * relu(a0*A2[0,i*64+o] + a1*A2[1,i*64+o] + b2[i*64+o])
// 128 threads: thread = (o = tid&63, g = tid>>6). A2/b2 slice in 96 regs.
// ---------------------------------------------------------------------------
#define L2_EPB 4

__global__ __launch_bounds__(128, 3)
void k_edge2(const int* __restrict__ ei,
             const float* __restrict__ ea,
             const float* __restrict__ A2,
             const float* __restrict__ b2,
             float* __restrict__ out,
             int E, int N)
{
    const int tid = threadIdx.x;
    const int o = tid & 63;
    const int g = tid >> 6;  // 0 or 1

    float A0r[32], A1r[32], Br[32];
#pragma unroll
    for (int k = 0; k < 32; k++) {
        int col = (g * 32 + k) * 64 + o;
        A0r[k] = __ldg(&A2[col]);
        A1r[k] = __ldg(&A2[4096 + col]);
        Br[k]  = __ldg(&b2[col]);
    }

    __shared__ float hs[L2_EPB][64];
    __shared__ float pr[L2_EPB][64];
    __shared__ float msg[L2_EPB][64];
    __shared__ int   sSrc[L2_EPB];
    __shared__ int   sDst[L2_EPB];
    __shared__ float sA0[L2_EPB];
    __shared__ float sA1[L2_EPB];

    for (int e0 = blockIdx.x * L2_EPB; e0 < E; e0 += gridDim.x * L2_EPB) {
        if (tid < L2_EPB) {
            int e = e0 + tid;
            if (e < E) {
                sSrc[tid] = clamp_idx(ei[e], N);
                sDst[tid] = clamp_idx(ei[E + e], N);
                float2 a = *reinterpret_cast<const float2*>(ea + 2 * e);
                sA0[tid] = a.x;
                sA1[tid] = a.y;
            } else {
                sSrc[tid] = 0;
                sDst[tid] = 0;
                sA0[tid] = 0.0f;
                sA1[tid] = 0.0f;
            }
        }
        __syncthreads();

        // Gather h[src] rows: 4 edges x 64 floats, 128 threads x 2.
        {
            int idx = tid;
#pragma unroll
            for (int r = 0; r < 2; r++) {
                int j = idx >> 6, c = idx & 63;
                hs[j][c] = g_h[(size_t)sSrc[j] * 64 + c];
                idx += 128;
            }
        }
        __syncthreads();

        float a0[L2_EPB], a1[L2_EPB], acc[L2_EPB];
#pragma unroll
        for (int j = 0; j < L2_EPB; j++) {
            a0[j] = sA0[j];
            a1[j] = sA1[j];
            acc[j] = 0.0f;
        }

#pragma unroll
        for (int k = 0; k < 32; k++) {
#pragma unroll
            for (int j = 0; j < L2_EPB; j++) {
                float w = fmaf(a1[j], A1r[k], fmaf(a0[j], A0r[k], Br[k]));
                w = fmaxf(w, 0.0f);
                acc[j] = fmaf(hs[j][g * 32 + k], w, acc[j]);
            }
        }

        if (g == 1) {
#pragma unroll
            for (int j = 0; j < L2_EPB; j++) pr[j][o] = acc[j];
        }
        __syncthreads();
        if (g == 0) {
#pragma unroll
            for (int j = 0; j < L2_EPB; j++) msg[j][o] = acc[j] + pr[j][o];
        }
        __syncthreads();

        if (tid < 64) {
            int j = tid >> 4, q = tid & 15;
            if (e0 + j < E) {
                float4 v = *reinterpret_cast<const float4*>(&msg[j][q * 4]);
                float* dstp = out + (size_t)sDst[j] * 64 + q * 4;
                asm volatile("red.global.add.v4.f32 [%0], {%1, %2, %3, %4};"
                             :: "l"(dstp), "f"(v.x), "f"(v.y), "f"(v.z), "f"(v.w)
                             : "memory");
            }
        }
        __syncthreads();
    }
}

// ---------------------------------------------------------------------------
// Launch
// ---------------------------------------------------------------------------
extern "C" void kernel_launch(void* const* d_in, const int* in_sizes, int n_in,
                              void* d_out, int out_size)
{
    const float* x     = (const float*)d_in[0];
    const int*   ei    = (const int*)d_in[1];     // int32 (JAX x64 disabled)
    const float* ea    = (const float*)d_in[2];
    const float* A1    = (const float*)d_in[3];
    const float* b1    = (const float*)d_in[4];
    const float* A2    = (const float*)d_in[5];
    const float* b2    = (const float*)d_in[6];
    const float* root1 = (const float*)d_in[7];
    const float* bias1 = (const float*)d_in[8];
    const float* root2 = (const float*)d_in[9];
    const float* bias2 = (const float*)d_in[10];
    float* out = (float*)d_out;

    const int N = in_sizes[0] / C1_IN;   // 16384
    const int E = in_sizes[1] / 2;       // 65536

    {
        int total = N * 64;
        int blocks = (total + 255) / 256;
        k_node1<<<blocks, 256>>>(x, root1, bias1, N);
    }
    k_edge1<<<1024, 256>>>(x, ei, ea, A1, b1, E, N);
    k_node2<<<512, 256>>>(root2, bias2, out, N);
    k_edge2<<<444, 128>>>(ei, ea, A2, b2, out, E, N);
}

// round 6
// speedup vs baseline: 1.2988x; 1.2953x over previous
#include <cuda_runtime.h>
#include <cuda_bf16.h>
#include <cstdint>

#define C1_IN 8
#define NN 16384

__device__ float g_h[NN * 64];

__device__ __forceinline__ int clamp_idx(int v, int n) {
    v = v < 0 ? 0 : v;
    return v >= n ? n - 1 : v;
}

__device__ __forceinline__ unsigned long long pk2(float lo, float hi) {
    unsigned long long r;
    asm("mov.b64 %0, {%1, %2};" : "=l"(r) : "f"(lo), "f"(hi));
    return r;
}
__device__ __forceinline__ void upk2(unsigned long long v, float& lo, float& hi) {
    asm("mov.b64 {%0, %1}, %2;" : "=f"(lo), "=f"(hi) : "l"(v));
}
__device__ __forceinline__ unsigned long long ffma2(unsigned long long a,
                                                    unsigned long long b,
                                                    unsigned long long c) {
    unsigned long long d;
    asm("fma.rn.f32x2 %0, %1, %2, %3;" : "=l"(d) : "l"(a), "l"(b), "l"(c));
    return d;
}

// ---------------------------------------------------------------------------
// K1: h[n,o] = sum_i x[n,i] * root1[i,o] + bias1[o]
// ---------------------------------------------------------------------------
__global__ void k_node1(const float* __restrict__ x,
                        const float* __restrict__ root1,
                        const float* __restrict__ bias1,
                        int N)
{
    int idx = blockIdx.x * blockDim.x + threadIdx.x;
    if (idx >= N * 64) return;
    int n = idx >> 6;
    int o = idx & 63;
    const float* xr = x + n * C1_IN;
    float acc = __ldg(&bias1[o]);
#pragma unroll
    for (int i = 0; i < C1_IN; i++)
        acc = fmaf(__ldg(&xr[i]), __ldg(&root1[i * 64 + o]), acc);
    g_h[idx] = acc;
}

// ---------------------------------------------------------------------------
// K2: layer-1 edge kernel. Fully warp-autonomous: lane owns cols (2l, 2l+1),
// full k=0..7 in 48 weight regs (packed along col-pair). No smem, no barriers.
// ---------------------------------------------------------------------------
__global__ __launch_bounds__(256)
void k_edge1(const float* __restrict__ x,
             const int* __restrict__ ei,
             const float* __restrict__ ea,
             const float* __restrict__ A1,
             const float* __restrict__ b1,
             int E, int N)
{
    const int lane = threadIdx.x & 31;
    const int c0 = 2 * lane;

    unsigned long long A0p[8], A1p[8], Bp[8];
#pragma unroll
    for (int k = 0; k < 8; k++) {
        A0p[k] = pk2(__ldg(&A1[k * 64 + c0]),       __ldg(&A1[k * 64 + c0 + 1]));
        A1p[k] = pk2(__ldg(&A1[512 + k * 64 + c0]), __ldg(&A1[512 + k * 64 + c0 + 1]));
        Bp[k]  = pk2(__ldg(&b1[k * 64 + c0]),       __ldg(&b1[k * 64 + c0 + 1]));
    }

    const int gw = (blockIdx.x * blockDim.x + threadIdx.x) >> 5;
    const int nw = (gridDim.x * blockDim.x) >> 5;

    for (int e = gw; e < E; e += nw) {
        int src = clamp_idx(__ldg(&ei[e]), N);
        int dst = clamp_idx(__ldg(&ei[E + e]), N);
        float2 a = __ldg(reinterpret_cast<const float2*>(ea) + e);
        unsigned long long a0p = pk2(a.x, a.x);
        unsigned long long a1p = pk2(a.y, a.y);

        float xv = (lane < C1_IN) ? __ldg(&x[src * C1_IN + lane]) : 0.0f;

        float acc0 = 0.0f, acc1 = 0.0f;
#pragma unroll
        for (int k = 0; k < 8; k++) {
            float xk = __shfl_sync(0xffffffffu, xv, k);
            unsigned long long w = ffma2(a1p, A1p[k], ffma2(a0p, A0p[k], Bp[k]));
            float wl, wh;
            upk2(w, wl, wh);
            acc0 = fmaf(fmaxf(wl, 0.0f), xk, acc0);
            acc1 = fmaf(fmaxf(wh, 0.0f), xk, acc1);
        }
        float* p = g_h + (size_t)dst * 64 + c0;
        asm volatile("red.global.add.v2.f32 [%0], {%1, %2};"
                     :: "l"(p), "f"(acc0), "f"(acc1) : "memory");
    }
}

// ---------------------------------------------------------------------------
// K3: out[n,o] = sum_i h[n,i] * root2[i,o] + bias2[o]
// Packed f32x2 over col-pairs; thread = (col-pair op, node offset j).
// ---------------------------------------------------------------------------
__global__ __launch_bounds__(256)
void k_node2(const float* __restrict__ root2,
             const float* __restrict__ bias2,
             float* __restrict__ out,
             int N)
{
    __shared__ __align__(16) float r2[4096];
    for (int i = threadIdx.x; i < 4096; i += blockDim.x)
        r2[i] = root2[i];
    __syncthreads();

    const int op = threadIdx.x & 31;   // col pair: cols (2*op, 2*op+1)
    const int j  = threadIdx.x >> 5;   // 0..7
    float2 bv = __ldg(reinterpret_cast<const float2*>(bias2) + op);
    const unsigned long long bp = pk2(bv.x, bv.y);
    const unsigned long long* r2p = reinterpret_cast<const unsigned long long*>(r2);

    for (int nb = blockIdx.x * 8; nb < N; nb += gridDim.x * 8) {
        int n = nb + j;
        const float4* hr = reinterpret_cast<const float4*>(g_h + (size_t)n * 64);
        unsigned long long acc = bp;
#pragma unroll
        for (int q = 0; q < 16; q++) {
            float4 hv = hr[q];
            acc = ffma2(pk2(hv.x, hv.x), r2p[(q * 4 + 0) * 32 + op], acc);
            acc = ffma2(pk2(hv.y, hv.y), r2p[(q * 4 + 1) * 32 + op], acc);
            acc = ffma2(pk2(hv.z, hv.z), r2p[(q * 4 + 2) * 32 + op], acc);
            acc = ffma2(pk2(hv.w, hv.w), r2p[(q * 4 + 3) * 32 + op], acc);
        }
        float ol, oh;
        upk2(acc, ol, oh);
        float2* po = reinterpret_cast<float2*>(out + (size_t)n * 64) + op;
        *po = make_float2(ol, oh);
    }
}

// ---------------------------------------------------------------------------
// K4: layer-2 edge kernel (the heavy one).
// Block = 128 threads = 4 warps. Warp w owns cols [w*16, w*16+16).
// Thread = (col = w*16 + (lane&15), k-half g = lane>>4), k in [g*32, g*32+32)
// as 16 packed k-pairs (96 weight regs, packed f32x2 W-eval).
// Double-buffered h gather + edge meta; ONE barrier per 8-edge batch.
// Cross-k reduce = shfl_xor(16); scatter = predicated scalar red.global.add.
// ---------------------------------------------------------------------------
#define EPB 8

__global__ __launch_bounds__(128, 4)
void k_edge2(const int* __restrict__ ei,
             const float* __restrict__ ea,
             const float* __restrict__ A2,
             const float* __restrict__ b2,
             float* __restrict__ out,
             int E, int N)
{
    const int tid  = threadIdx.x;
    const int warp = tid >> 5;
    const int lane = tid & 31;
    const int col  = warp * 16 + (lane & 15);
    const int g    = lane >> 4;       // k half
    const int kbase = g * 32;

    // Pre-pack weights: 16 k-pairs for this thread's column.
    unsigned long long A0p[16], A1p[16], Bp[16];
#pragma unroll
    for (int kk = 0; kk < 16; kk++) {
        int k0 = kbase + 2 * kk;
        A0p[kk] = pk2(__ldg(&A2[k0 * 64 + col]),        __ldg(&A2[(k0 + 1) * 64 + col]));
        A1p[kk] = pk2(__ldg(&A2[4096 + k0 * 64 + col]), __ldg(&A2[4096 + (k0 + 1) * 64 + col]));
        Bp[kk]  = pk2(__ldg(&b2[k0 * 64 + col]),        __ldg(&b2[(k0 + 1) * 64 + col]));
    }

    __shared__ __align__(16) float hs[2][EPB][64];
    __shared__ float sA0[2][EPB];
    __shared__ float sA1[2][EPB];
    __shared__ int   sDst[2][EPB];

    const int nbatch = (E + EPB - 1) / EPB;
    const int gj = tid >> 4;   // 0..7: edge row for gather
    const int gq = tid & 15;   // float4 quad within row

    // Loads one batch's h rows + edge meta into buffer buf.
    auto load_batch = [&](int b, int buf) {
        int e = b * EPB + gj;
        int src = 0;
        if (e < E) src = clamp_idx(__ldg(&ei[e]), N);
        const float4* p = reinterpret_cast<const float4*>(g_h + (size_t)src * 64);
        reinterpret_cast<float4*>(&hs[buf][gj][0])[gq] = p[gq];
        if (tid < EPB) {
            int em = b * EPB + tid;
            float a0 = 0.0f, a1 = 0.0f;
            int dst = 0;
            if (em < E) {
                float2 a = __ldg(reinterpret_cast<const float2*>(ea) + em);
                a0 = a.x; a1 = a.y;
                dst = clamp_idx(__ldg(&ei[E + em]), N);
            }
            sA0[buf][tid] = a0;
            sA1[buf][tid] = a1;
            sDst[buf][tid] = dst;
        }
    };

    int b = blockIdx.x;
    int buf = 0;
    if (b < nbatch) load_batch(b, 0);
    __syncthreads();

    while (b < nbatch) {
        int bn = b + gridDim.x;
        if (bn < nbatch) load_batch(bn, buf ^ 1);

        int e0 = b * EPB;
#pragma unroll 2
        for (int j = 0; j < EPB; j++) {
            float a0 = sA0[buf][j];
            float a1 = sA1[buf][j];
            unsigned long long a0p = pk2(a0, a0);
            unsigned long long a1p = pk2(a1, a1);
            const unsigned long long* hp =
                reinterpret_cast<const unsigned long long*>(&hs[buf][j][kbase]);

            float acc = 0.0f;
#pragma unroll
            for (int kk = 0; kk < 16; kk++) {
                unsigned long long w = ffma2(a1p, A1p[kk], ffma2(a0p, A0p[kk], Bp[kk]));
                float wl, wh;
                upk2(w, wl, wh);
                float hl, hh;
                upk2(hp[kk], hl, hh);
                acc = fmaf(fmaxf(wl, 0.0f), hl, acc);
                acc = fmaf(fmaxf(wh, 0.0f), hh, acc);
            }
            // combine the two k halves
            acc += __shfl_xor_sync(0xffffffffu, acc, 16);
            if (g == 0 && (e0 + j) < E) {
                float* p = out + (size_t)sDst[buf][j] * 64 + col;
                asm volatile("red.global.add.f32 [%0], %1;"
                             :: "l"(p), "f"(acc) : "memory");
            }
        }
        __syncthreads();
        buf ^= 1;
        b = bn;
    }
}

// ---------------------------------------------------------------------------
// Launch
// ---------------------------------------------------------------------------
extern "C" void kernel_launch(void* const* d_in, const int* in_sizes, int n_in,
                              void* d_out, int out_size)
{
    const float* x     = (const float*)d_in[0];
    const int*   ei    = (const int*)d_in[1];
    const float* ea    = (const float*)d_in[2];
    const float* A1    = (const float*)d_in[3];
    const float* b1    = (const float*)d_in[4];
    const float* A2    = (const float*)d_in[5];
    const float* b2    = (const float*)d_in[6];
    const float* root1 = (const float*)d_in[7];
    const float* bias1 = (const float*)d_in[8];
    const float* root2 = (const float*)d_in[9];
    const float* bias2 = (const float*)d_in[10];
    float* out = (float*)d_out;

    const int N = in_sizes[0] / C1_IN;   // 16384
    const int E = in_sizes[1] / 2;       // 65536

    {
        int total = N * 64;
        int blocks = (total + 255) / 256;
        k_node1<<<blocks, 256>>>(x, root1, bias1, N);
    }
    k_edge1<<<296, 256>>>(x, ei, ea, A1, b1, E, N);
    k_node2<<<512, 256>>>(root2, bias2, out, N);
    k_edge2<<<592, 128>>>(ei, ea, A2, b2, out, E, N);
}